// round 2
// baseline (speedup 1.0000x reference)
#include <cuda_runtime.h>
#include <math.h>

// Problem constants
#define BB    64
#define WW    254
#define SS    256
#define DPHO  768
#define DIN   968          // 100 + 768 + 100
#define HH    256
#define NG    1024         // 4*H
#define ROWS  (BB*WW)      // 16256

// Output layout (tuple flattened): rnn1_out [B,W,512] | hf [B,W,256] | hb [B,W,256]
#define OUT_RNN1_SZ  ((size_t)ROWS * 512)          // 8,323,072
#define OUT_H_SZ     ((size_t)ROWS * HH)           // 4,161,536
#define OUT_TOTAL    (OUT_RNN1_SZ + 2*OUT_H_SZ)    // 16,646,144

// Scratch (static __device__ globals: allowed; no runtime allocation)
__device__ float g_emb[(size_t)ROWS * DIN];        // [16256, 968]   ~63 MB
__device__ float g_xp [(size_t)2 * ROWS * NG];     // [2, 16256, 1024] ~133 MB
__device__ float g_h  [(size_t)2 * ROWS * HH];     // h history per dir ~33 MB
__device__ float g_c  [2 * BB * HH];               // cell state per dir

// ---------------------------------------------------------------------------
// Kernel 1: build emb = [word_emb(100) | pho_span_sum(768) | pos_emb(100)]
// One block per (b, w). searchsorted-right segment semantics reduce exactly to
// the interval form: word w sums features[b, lip[w]:lip[w+1]] (duplicate
// boundaries give empty intervals, matching the reference).
// ---------------------------------------------------------------------------
__global__ void embed_kernel(const int* __restrict__ words,
                             const float* __restrict__ features,
                             const int* __restrict__ lip,
                             const int* __restrict__ postags,
                             const float* __restrict__ word_table,
                             const float* __restrict__ pos_table)
{
    int bw = blockIdx.x;            // b*WW + w
    int b  = bw / WW;
    int w  = bw - b * WW;
    int tid = threadIdx.x;          // 128 threads

    float* row = g_emb + (size_t)bw * DIN;

    int wid = words[bw];
    int pid = postags[bw];
    for (int d = tid; d < 100; d += 128) {
        row[d]       = word_table[wid * 100 + d];
        row[868 + d] = pos_table [pid * 100 + d];
    }

    int s0 = lip[b * (WW + 2) + w];
    int s1 = lip[b * (WW + 2) + w + 1];
    if (s1 > SS) s1 = SS;
    if (s0 < 0)  s0 = 0;

    for (int d = tid; d < DPHO; d += 128) {
        float acc = 0.f;
        for (int t = s0; t < s1; ++t)
            acc += features[((size_t)b * SS + t) * DPHO + d];
        row[100 + d] = acc;
    }
}

// ---------------------------------------------------------------------------
// Kernel 2: input projection  xp[dir] = emb @ w_ih[dir]^T + bias[dir]
// fp32 SIMT tiled GEMM: BM=128, BN=64, BK=8, 256 threads, 8x4 per thread.
// M=16256 (=128*127), N=1024 (=64*16), K=968 (=8*121): no edge guards needed.
// ---------------------------------------------------------------------------
__global__ void __launch_bounds__(256)
input_gemm_kernel(const float* __restrict__ w0, const float* __restrict__ w1,
                  const float* __restrict__ b0, const float* __restrict__ b1)
{
    __shared__ float As[8][128];
    __shared__ float Bs[8][64];

    int dir = blockIdx.z;
    const float* Wm   = dir ? w1 : w0;
    const float* bias = dir ? b1 : b0;

    int m0 = blockIdx.y * 128;
    int n0 = blockIdx.x * 64;
    int tid = threadIdx.x;

    int trow = tid >> 4;            // 0..15 (8 rows each)
    int tcol = tid & 15;            // 0..15 (4 cols each)

    int arow = tid >> 1;            // 0..127
    int akk  = (tid & 1) << 2;      // 0 or 4
    int brow = tid >> 2;            // 0..63
    int bkk  = (tid & 3) << 1;      // 0,2,4,6

    const float* Ap = g_emb + (size_t)(m0 + arow) * DIN + akk;
    const float* Bp = Wm    + (size_t)(n0 + brow) * DIN + bkk;

    float acc[8][4];
#pragma unroll
    for (int i = 0; i < 8; ++i)
#pragma unroll
        for (int j = 0; j < 4; ++j) acc[i][j] = 0.f;

    for (int k0 = 0; k0 < DIN; k0 += 8) {
        float4 av = *reinterpret_cast<const float4*>(Ap + k0);
        float2 bv = *reinterpret_cast<const float2*>(Bp + k0);
        __syncthreads();
        As[akk + 0][arow] = av.x;
        As[akk + 1][arow] = av.y;
        As[akk + 2][arow] = av.z;
        As[akk + 3][arow] = av.w;
        Bs[bkk + 0][brow] = bv.x;
        Bs[bkk + 1][brow] = bv.y;
        __syncthreads();
#pragma unroll
        for (int k = 0; k < 8; ++k) {
            float a[8], bq[4];
#pragma unroll
            for (int i = 0; i < 8; ++i) a[i] = As[k][(trow << 3) + i];
#pragma unroll
            for (int j = 0; j < 4; ++j) bq[j] = Bs[k][(tcol << 2) + j];
#pragma unroll
            for (int i = 0; i < 8; ++i)
#pragma unroll
                for (int j = 0; j < 4; ++j)
                    acc[i][j] = fmaf(a[i], bq[j], acc[i][j]);
        }
    }

    float* C = g_xp + (size_t)dir * ROWS * NG;
#pragma unroll
    for (int i = 0; i < 8; ++i) {
        int m = m0 + (trow << 3) + i;
        float* crow = C + (size_t)m * NG + n0 + (tcol << 2);
#pragma unroll
        for (int j = 0; j < 4; ++j)
            crow[j] = acc[i][j] + bias[n0 + (tcol << 2) + j];
    }
}

// ---------------------------------------------------------------------------
// Kernel 3: one LSTM timestep, both directions in one launch.
// Grid: (jt=16, bt=4, dir=2) = 128 blocks, 256 threads.
// Block owns 16 j-columns (=> 64 gate rows of w_hh) and 16 batch rows.
// The 256-wide K reduction is processed in TWO chunks of 128 so the whole
// kernel fits in 41.4 KB STATIC shared memory (no cudaFuncSetAttribute,
// no dynamic-smem opt-in). Kernel boundary = per-step recurrence sync.
// ---------------------------------------------------------------------------
__global__ void __launch_bounds__(256)
lstm_step_kernel(const float* __restrict__ whhF, const float* __restrict__ whhB,
                 float* __restrict__ out, int kstep, int write_full)
{
    __shared__ float Wsh[128 * 65];    // [kk][r], pitch 65: conflict-free stage
    __shared__ float Hsh[16 * 128];    // [bl][kk] h_prev tile for this chunk

    int dir = blockIdx.z;
    int t     = dir ? (WW - 1 - kstep) : kstep;
    int tprev = dir ? (t + 1) : (t - 1);
    const float* whh = dir ? whhB : whhF;

    int jt = blockIdx.x;               // 0..15
    int bt = blockIdx.y;               // 0..3
    int tid = threadIdx.x;

    int bl = tid >> 4, jl = tid & 15;
    int bg = (bt << 4) + bl;           // global batch 0..63
    int jg = (jt << 4) + jl;           // global j 0..255

    const float* xrow = g_xp + ((size_t)dir * ROWS + (size_t)bg * WW + t) * NG;
    float a0 = xrow[jg];               // i gate
    float a1 = xrow[256 + jg];         // f gate
    float a2 = xrow[512 + jg];         // g gate
    float a3 = xrow[768 + jg];         // o gate

    float* hhist = g_h + (size_t)dir * ROWS * HH;

    for (int kc = 0; kc < 256; kc += 128) {
        // Stage 64 weight rows x 128 k, transposed: Wsh[kk*65 + r]
        // r = gate*16 + jl_local maps to whh row (gate*256 + jt*16 + jl_local)
        for (int idx = tid; idx < 64 * 128; idx += 256) {
            int r  = idx >> 7;         // local row 0..63
            int kk = idx & 127;
            int gate = r >> 4, jloc = r & 15;
            Wsh[kk * 65 + r] = whh[((gate << 8) + (jt << 4) + jloc) * 256 + kc + kk];
        }
        // Stage h_prev chunk for this block's 16 batches
        for (int idx = tid; idx < 16 * 128; idx += 256) {
            int bloc = idx >> 7, kk = idx & 127;
            int bgl = (bt << 4) + bloc;
            Hsh[bloc * 128 + kk] =
                (kstep == 0) ? 0.f : hhist[((size_t)bgl * WW + tprev) * HH + kc + kk];
        }
        __syncthreads();

        const float* hr = Hsh + bl * 128;
#pragma unroll 4
        for (int kk = 0; kk < 128; ++kk) {
            float hv = hr[kk];
            const float* wk = Wsh + kk * 65;
            a0 = fmaf(wk[jl],      hv, a0);
            a1 = fmaf(wk[16 + jl], hv, a1);
            a2 = fmaf(wk[32 + jl], hv, a2);
            a3 = fmaf(wk[48 + jl], hv, a3);
        }
        __syncthreads();               // protect smem before next chunk restage
    }

    int cidx = ((dir * BB + bg) << 8) + jg;
    float cp = (kstep == 0) ? 0.f : g_c[cidx];

    float ig = 1.f / (1.f + expf(-a0));
    float fg = 1.f / (1.f + expf(-a1));
    float gg = tanhf(a2);
    float og = 1.f / (1.f + expf(-a3));
    float c  = fg * cp + ig * gg;
    float h  = og * tanhf(c);

    g_c[cidx] = c;

    size_t bw = (size_t)bg * WW + t;
    hhist[bw * HH + jg] = h;                           // recurrence history
    out[bw * 512 + (dir << 8) + jg] = h;               // rnn1_out [B,W,2H]
    if (write_full)
        out[OUT_RNN1_SZ + (size_t)dir * OUT_H_SZ + bw * HH + jg] = h;  // hf / hb
}

// ---------------------------------------------------------------------------
extern "C" void kernel_launch(void* const* d_in, const int* in_sizes, int n_in,
                              void* d_out, int out_size)
{
    const int*   words      = (const int*)  d_in[0];
    const float* features   = (const float*)d_in[1];
    const int*   lip        = (const int*)  d_in[2];
    const int*   postags    = (const int*)  d_in[3];
    // d_in[4] = chars (unused), d_in[5] = masks (unused)
    const float* word_table = (const float*)d_in[6];
    const float* pos_table  = (const float*)d_in[7];
    const float* w_ih_f     = (const float*)d_in[8];
    const float* w_hh_f     = (const float*)d_in[9];
    const float* b_f        = (const float*)d_in[10];
    const float* w_ih_b     = (const float*)d_in[11];
    const float* w_hh_b     = (const float*)d_in[12];
    const float* b_b        = (const float*)d_in[13];
    float* out = (float*)d_out;

    int write_full = ((size_t)out_size >= OUT_TOTAL) ? 1 : 0;

    // Phase 1: embeddings
    embed_kernel<<<ROWS, 128>>>(words, features, lip, postags, word_table, pos_table);

    // Phase 2: input projections for both directions
    input_gemm_kernel<<<dim3(16, 127, 2), 256>>>(w_ih_f, w_ih_b, b_f, b_b);

    // Phase 3: recurrence, one launch per timestep (fwd t=k, bwd t=W-1-k)
    for (int k = 0; k < WW; ++k)
        lstm_step_kernel<<<dim3(16, 4, 2), 256>>>(w_hh_f, w_hh_b, out, k, write_full);
}

// round 3
// speedup vs baseline: 1.4546x; 1.4546x over previous
#include <cuda_runtime.h>
#include <math.h>

// Problem constants
#define BB    64
#define WW    254
#define SS    256
#define DPHO  768
#define DIN   968          // 100 + 768 + 100
#define HH    256
#define NG    1024         // 4*H
#define ROWS  (BB*WW)      // 16256
#define NBLK  256          // persistent LSTM grid size

// Output layout: rnn1_out [B,W,512] | hf [B,W,256] | hb [B,W,256]
#define OUT_RNN1_SZ  ((size_t)ROWS * 512)
#define OUT_H_SZ     ((size_t)ROWS * HH)
#define OUT_TOTAL    (OUT_RNN1_SZ + 2*OUT_H_SZ)

// Scratch (__device__ globals: allowed; no runtime allocation)
__device__ float    g_emb[(size_t)ROWS * DIN];      // [16256, 968]
__device__ float    g_xp [(size_t)2 * ROWS * NG];   // [2, 16256, 1024]
__device__ float    g_hstate[2][2][BB][HH];         // [phase][dir][b][k] double-buffered
__device__ unsigned g_bar;                          // grid barrier counter

// ---- packed f32x2 helpers (Blackwell; ptxas won't auto-fuse, PTX only) ----
__device__ __forceinline__ void fma2(unsigned long long& acc,
                                     unsigned long long a, unsigned long long b) {
    asm("fma.rn.f32x2 %0, %1, %2, %0;" : "+l"(acc) : "l"(a), "l"(b));
}
__device__ __forceinline__ unsigned long long packdup(float x) {
    unsigned long long r;
    asm("mov.b64 %0, {%1, %1};" : "=l"(r) : "f"(x));
    return r;
}
__device__ __forceinline__ float2 unpack2(unsigned long long v) {
    float2 f;
    asm("mov.b64 {%0, %1}, %2;" : "=f"(f.x), "=f"(f.y) : "l"(v));
    return f;
}

// ---------------------------------------------------------------------------
// Kernel 1: emb = [word_emb(100) | pho_span_sum(768) | pos_emb(100)]
// searchsorted-right segment semantics == interval sum [lip[w], lip[w+1]).
// Also resets the persistent-kernel grid barrier (runs before it each launch).
// ---------------------------------------------------------------------------
__global__ void embed_kernel(const int* __restrict__ words,
                             const float* __restrict__ features,
                             const int* __restrict__ lip,
                             const int* __restrict__ postags,
                             const float* __restrict__ word_table,
                             const float* __restrict__ pos_table)
{
    if (blockIdx.x == 0 && threadIdx.x == 0) g_bar = 0;

    int bw = blockIdx.x;
    int b  = bw / WW;
    int w  = bw - b * WW;
    int tid = threadIdx.x;          // 128 threads

    float* row = g_emb + (size_t)bw * DIN;
    int wid = words[bw];
    int pid = postags[bw];
    for (int d = tid; d < 100; d += 128) {
        row[d]       = word_table[wid * 100 + d];
        row[868 + d] = pos_table [pid * 100 + d];
    }

    int s0 = lip[b * (WW + 2) + w];
    int s1 = lip[b * (WW + 2) + w + 1];
    if (s1 > SS) s1 = SS;
    if (s0 < 0)  s0 = 0;

    for (int d = tid; d < DPHO; d += 128) {
        float acc = 0.f;
        for (int t = s0; t < s1; ++t)
            acc += features[((size_t)b * SS + t) * DPHO + d];
        row[100 + d] = acc;
    }
}

// ---------------------------------------------------------------------------
// Kernel 2: xp[dir] = emb @ w_ih[dir]^T + bias[dir]
// 128x128x8 tile, 256 threads, 8x8 microtile via fma.rn.f32x2.
// M=16256=127*128, N=1024=8*128, K=968=121*8: exact, no guards.
// ---------------------------------------------------------------------------
__global__ void __launch_bounds__(256, 2)
input_gemm_kernel(const float* __restrict__ w0, const float* __restrict__ w1,
                  const float* __restrict__ b0, const float* __restrict__ b1)
{
    __shared__ float As[8][128];
    __shared__ float Bs[8][128];

    int dir = blockIdx.z;
    const float* Wm   = dir ? w1 : w0;
    const float* bias = dir ? b1 : b0;

    int m0 = blockIdx.y * 128;
    int n0 = blockIdx.x * 128;
    int tid = threadIdx.x;

    int arow = tid >> 1;            // 0..127
    int ak   = (tid & 1) << 2;      // 0 or 4
    int tx   = tid & 15;            // col group
    int ty   = tid >> 4;            // row group

    const float* Ap = g_emb + (size_t)(m0 + arow) * DIN + ak;
    const float* Bp = Wm    + (size_t)(n0 + arow) * DIN + ak;

    unsigned long long acc[8][4];   // 8 rows x 8 cols as 4 f32x2 pairs
#pragma unroll
    for (int i = 0; i < 8; ++i)
#pragma unroll
        for (int j = 0; j < 4; ++j) acc[i][j] = 0ULL;

    for (int k0 = 0; k0 < DIN; k0 += 8) {
        float4 av = *reinterpret_cast<const float4*>(Ap + k0);
        float4 bv = *reinterpret_cast<const float4*>(Bp + k0);
        __syncthreads();
        As[ak + 0][arow] = av.x;  As[ak + 1][arow] = av.y;
        As[ak + 2][arow] = av.z;  As[ak + 3][arow] = av.w;
        Bs[ak + 0][arow] = bv.x;  Bs[ak + 1][arow] = bv.y;
        Bs[ak + 2][arow] = bv.z;  Bs[ak + 3][arow] = bv.w;
        __syncthreads();
#pragma unroll
        for (int k = 0; k < 8; ++k) {
            float4 alo = *reinterpret_cast<const float4*>(&As[k][ty * 4]);
            float4 ahi = *reinterpret_cast<const float4*>(&As[k][64 + ty * 4]);
            ulonglong2 blo = *reinterpret_cast<const ulonglong2*>(&Bs[k][tx * 4]);
            ulonglong2 bhi = *reinterpret_cast<const ulonglong2*>(&Bs[k][64 + tx * 4]);
            unsigned long long a2[8];
            a2[0] = packdup(alo.x); a2[1] = packdup(alo.y);
            a2[2] = packdup(alo.z); a2[3] = packdup(alo.w);
            a2[4] = packdup(ahi.x); a2[5] = packdup(ahi.y);
            a2[6] = packdup(ahi.z); a2[7] = packdup(ahi.w);
#pragma unroll
            for (int i = 0; i < 8; ++i) {
                fma2(acc[i][0], a2[i], blo.x);
                fma2(acc[i][1], a2[i], blo.y);
                fma2(acc[i][2], a2[i], bhi.x);
                fma2(acc[i][3], a2[i], bhi.y);
            }
        }
    }

    float4 bz_lo = *reinterpret_cast<const float4*>(bias + n0 + tx * 4);
    float4 bz_hi = *reinterpret_cast<const float4*>(bias + n0 + 64 + tx * 4);

    float* C = g_xp + (size_t)dir * ROWS * NG;
#pragma unroll
    for (int i = 0; i < 8; ++i) {
        int m = m0 + ((i < 4) ? (ty * 4 + i) : (64 + ty * 4 + i - 4));
        float2 u0 = unpack2(acc[i][0]);
        float2 u1 = unpack2(acc[i][1]);
        float2 u2 = unpack2(acc[i][2]);
        float2 u3 = unpack2(acc[i][3]);
        float4 vlo = make_float4(u0.x + bz_lo.x, u0.y + bz_lo.y,
                                 u1.x + bz_lo.z, u1.y + bz_lo.w);
        float4 vhi = make_float4(u2.x + bz_hi.x, u2.y + bz_hi.y,
                                 u3.x + bz_hi.z, u3.y + bz_hi.w);
        *reinterpret_cast<float4*>(C + (size_t)m * NG + n0 + tx * 4)      = vlo;
        *reinterpret_cast<float4*>(C + (size_t)m * NG + n0 + 64 + tx * 4) = vhi;
    }
}

// ---------------------------------------------------------------------------
// Kernel 3: PERSISTENT bidirectional LSTM. One launch, 256 blocks (all
// co-resident: 48KB smem + <=128 regs -> >=2 blocks/SM * 148 SMs), software
// grid barrier per timestep. Weights staged to SMEM ONCE; h double-buffered
// in global (read with __ldcg: L1 not coherent across SMs); c in registers.
// Block = (jt 0..31: 8 j-cols -> 32 gate rows, bt 0..3: 16 batches, dir).
// Warp w owns local rows [4w,4w+4); lane = (b 0..15, rsel 0..1) -> 2 rows.
// SMEM layouts transposed ([kq][r], [kq][b]) -> conflict-free LDS.128.
// ---------------------------------------------------------------------------
__global__ void __launch_bounds__(256, 2)
lstm_persistent_kernel(const float* __restrict__ whhF,
                       const float* __restrict__ whhB,
                       float* __restrict__ out, int write_full)
{
    __shared__ ulonglong2 Wsh[64][32];   // 32 KB: [kq][local row]
    __shared__ ulonglong2 Hsh[64][16];   // 16 KB: [kq][local batch]; reused as Gsh

    int jt  = blockIdx.x;                // 0..31
    int bt  = blockIdx.y;                // 0..3
    int dir = blockIdx.z;
    int tid = threadIdx.x;
    const float* whh = dir ? whhB : whhF;

    // Stage weights once: local row r = gate*8 + jl  ->  whh row gate*256 + jt*8 + jl
    for (int idx = tid; idx < 32 * 64; idx += 256) {
        int r = idx >> 6, kq = idx & 63;
        int grow = ((r >> 3) << 8) + (jt << 3) + (r & 7);
        *reinterpret_cast<float4*>(&Wsh[kq][r]) =
            *reinterpret_cast<const float4*>(whh + (size_t)grow * 256 + kq * 4);
    }

    int l = tid & 31, w = tid >> 5;
    int bl = l & 15, rsel = l >> 4;
    int r0 = (w << 2) + (rsel << 1);     // local rows r0, r0+1

    // activation-phase mapping (threads < 128)
    int jl_a = tid >> 4;                 // 0..7
    int bl_a = tid & 15;                 // 0..15
    int bg_a = (bt << 4) + bl_a;
    int jg_a = (jt << 3) + jl_a;
    float c_reg = 0.f;

    float* Gsh = reinterpret_cast<float*>(Hsh);   // [r][b] 32x16 after k-loop

    const ulonglong2* hp = &Hsh[0][bl];
    const ulonglong2* wp = &Wsh[0][r0];

    for (int step = 0; step < WW; ++step) {
        int t = dir ? (WW - 1 - step) : step;
        int phase_r = step & 1;

        // prefetch xp gates for this step (overlaps with staging + k-loop)
        float x_i = 0.f, x_f = 0.f, x_g = 0.f, x_o = 0.f;
        if (tid < 128) {
            const float* xrow = g_xp + ((size_t)dir * ROWS + (size_t)bg_a * WW + t) * NG;
            x_i = __ldg(xrow + jg_a);
            x_f = __ldg(xrow + 256 + jg_a);
            x_g = __ldg(xrow + 512 + jg_a);
            x_o = __ldg(xrow + 768 + jg_a);
        }

        // stage h_prev tile (bypass L1: written by other SMs within this launch)
        if (step == 0) {
            for (int idx = tid; idx < 16 * 64; idx += 256) {
                int b = idx & 15, kq = idx >> 4;
                *reinterpret_cast<float4*>(&Hsh[kq][b]) = make_float4(0.f, 0.f, 0.f, 0.f);
            }
        } else {
            const float4* hsrc =
                reinterpret_cast<const float4*>(&g_hstate[phase_r][dir][bt << 4][0]);
            for (int idx = tid; idx < 16 * 64; idx += 256) {
                int b = idx & 15, kq = idx >> 4;
                *reinterpret_cast<float4*>(&Hsh[kq][b]) = __ldcg(hsrc + b * 64 + kq);
            }
        }
        __syncthreads();

        // dot products: 2 rows x 1 batch per lane over k=256 (f32x2 pairs)
        unsigned long long a00 = 0ULL, a01 = 0ULL, a10 = 0ULL, a11 = 0ULL;
#pragma unroll 16
        for (int kq = 0; kq < 64; ++kq) {
            ulonglong2 hv  = hp[kq * 16];
            ulonglong2 wv0 = wp[kq * 32];
            ulonglong2 wv1 = wp[kq * 32 + 1];
            fma2(a00, hv.x, wv0.x);  fma2(a01, hv.y, wv0.y);
            fma2(a10, hv.x, wv1.x);  fma2(a11, hv.y, wv1.y);
        }
        float2 p0 = unpack2(a00), p1 = unpack2(a01);
        float2 q0 = unpack2(a10), q1 = unpack2(a11);
        float dot0 = (p0.x + p0.y) + (p1.x + p1.y);
        float dot1 = (q0.x + q0.y) + (q1.x + q1.y);

        __syncthreads();                         // Hsh reads done; safe to reuse as Gsh
        Gsh[r0 * 16 + bl]       = dot0;
        Gsh[(r0 + 1) * 16 + bl] = dot1;
        __syncthreads();

        if (tid < 128) {
            float gi = x_i + Gsh[( 0 + jl_a) * 16 + bl_a];
            float gf = x_f + Gsh[( 8 + jl_a) * 16 + bl_a];
            float gg = x_g + Gsh[(16 + jl_a) * 16 + bl_a];
            float go = x_o + Gsh[(24 + jl_a) * 16 + bl_a];

            float ig = 1.f / (1.f + expf(-gi));
            float fg = 1.f / (1.f + expf(-gf));
            float tg = tanhf(gg);
            float og = 1.f / (1.f + expf(-go));
            c_reg = fg * c_reg + ig * tg;
            float h = og * tanhf(c_reg);

            g_hstate[phase_r ^ 1][dir][bg_a][jg_a] = h;
            size_t bw = (size_t)bg_a * WW + t;
            out[bw * 512 + (dir << 8) + jg_a] = h;
            if (write_full)
                out[OUT_RNN1_SZ + (size_t)dir * OUT_H_SZ + bw * HH + jg_a] = h;
        }

        // grid barrier (skip after final step)
        if (step < WW - 1) {
            __threadfence();
            __syncthreads();
            if (tid == 0) {
                atomicAdd(&g_bar, 1u);
                unsigned target = (unsigned)(step + 1) * NBLK;
                while (*reinterpret_cast<volatile unsigned*>(&g_bar) < target) { }
            }
            __syncthreads();
        }
    }
}

// ---------------------------------------------------------------------------
extern "C" void kernel_launch(void* const* d_in, const int* in_sizes, int n_in,
                              void* d_out, int out_size)
{
    const int*   words      = (const int*)  d_in[0];
    const float* features   = (const float*)d_in[1];
    const int*   lip        = (const int*)  d_in[2];
    const int*   postags    = (const int*)  d_in[3];
    // d_in[4] = chars (unused), d_in[5] = masks (unused)
    const float* word_table = (const float*)d_in[6];
    const float* pos_table  = (const float*)d_in[7];
    const float* w_ih_f     = (const float*)d_in[8];
    const float* w_hh_f     = (const float*)d_in[9];
    const float* b_f        = (const float*)d_in[10];
    const float* w_ih_b     = (const float*)d_in[11];
    const float* w_hh_b     = (const float*)d_in[12];
    const float* b_b        = (const float*)d_in[13];
    float* out = (float*)d_out;

    int write_full = ((size_t)out_size >= OUT_TOTAL) ? 1 : 0;

    // Phase 1: embeddings (+ barrier reset)
    embed_kernel<<<ROWS, 128>>>(words, features, lip, postags, word_table, pos_table);

    // Phase 2: input projections, f32x2 GEMM
    input_gemm_kernel<<<dim3(8, 127, 2), 256>>>(w_ih_f, w_ih_b, b_f, b_b);

    // Phase 3: persistent recurrence, single launch
    lstm_persistent_kernel<<<dim3(32, 4, 2), 256>>>(w_hh_f, w_hh_b, out, write_full);
}

// round 5
// speedup vs baseline: 1.6483x; 1.1332x over previous
#include <cuda_runtime.h>
#include <math.h>

// Problem constants
#define BB    64
#define WW    254
#define SS    256
#define DPHO  768
#define DIN   968          // 100 + 768 + 100
#define HH    256
#define NG    1024         // 4*H
#define ROWS  (BB*WW)      // 16256
#define NBLK  256          // persistent LSTM grid size

// Output layout: rnn1_out [B,W,512] | hf [B,W,256] | hb [B,W,256]
#define OUT_RNN1_SZ  ((size_t)ROWS * 512)
#define OUT_H_SZ     ((size_t)ROWS * HH)
#define OUT_TOTAL    (OUT_RNN1_SZ + 2*OUT_H_SZ)

// Scratch (__device__ globals: allowed; no runtime allocation)
__device__ float    g_emb[(size_t)ROWS * DIN];      // [16256, 968]
__device__ float    g_xp [(size_t)2 * ROWS * NG];   // [2, 16256, 1024]
// h state double-buffered, K-MAJOR for coalesced staging:
// [phase][dir][kq=64][b=64][ki=4]
__device__ float    g_h2[2][2][64][64][4];
__device__ unsigned g_bar;                          // grid barrier counter

// ---- packed f32x2 helpers (Blackwell; ptxas won't auto-fuse, PTX only) ----
__device__ __forceinline__ void fma2(unsigned long long& acc,
                                     unsigned long long a, unsigned long long b) {
    asm("fma.rn.f32x2 %0, %1, %2, %0;" : "+l"(acc) : "l"(a), "l"(b));
}
__device__ __forceinline__ unsigned long long packdup(float x) {
    unsigned long long r;
    asm("mov.b64 %0, {%1, %1};" : "=l"(r) : "f"(x));
    return r;
}
__device__ __forceinline__ float2 unpack2(unsigned long long v) {
    float2 f;
    asm("mov.b64 {%0, %1}, %2;" : "=f"(f.x), "=f"(f.y) : "l"(v));
    return f;
}

// ---------------------------------------------------------------------------
// Kernel 1: emb = [word_emb(100) | pho_span_sum(768) | pos_emb(100)]
// searchsorted-right segment semantics == interval sum [lip[w], lip[w+1]).
// Also resets the persistent-kernel grid barrier (stream order guarantees
// this completes before the persistent kernel starts, every graph replay).
// ---------------------------------------------------------------------------
__global__ void embed_kernel(const int* __restrict__ words,
                             const float* __restrict__ features,
                             const int* __restrict__ lip,
                             const int* __restrict__ postags,
                             const float* __restrict__ word_table,
                             const float* __restrict__ pos_table)
{
    if (blockIdx.x == 0 && threadIdx.x == 0) g_bar = 0;

    int bw = blockIdx.x;
    int b  = bw / WW;
    int w  = bw - b * WW;
    int tid = threadIdx.x;          // 128 threads

    float* row = g_emb + (size_t)bw * DIN;
    int wid = words[bw];
    int pid = postags[bw];
    for (int d = tid; d < 100; d += 128) {
        row[d]       = word_table[wid * 100 + d];
        row[868 + d] = pos_table [pid * 100 + d];
    }

    int s0 = lip[b * (WW + 2) + w];
    int s1 = lip[b * (WW + 2) + w + 1];
    if (s1 > SS) s1 = SS;
    if (s0 < 0)  s0 = 0;

    for (int d = tid; d < DPHO; d += 128) {
        float acc = 0.f;
        for (int t = s0; t < s1; ++t)
            acc += features[((size_t)b * SS + t) * DPHO + d];
        row[100 + d] = acc;
    }
}

// ---------------------------------------------------------------------------
// Kernel 2: xp[dir] = emb @ w_ih[dir]^T + bias[dir]
// 128x128x8 tile, 256 threads, 8x8 microtile via fma.rn.f32x2.
// Global->reg prefetch of next k-tile overlaps the compute phase.
// ---------------------------------------------------------------------------
__global__ void __launch_bounds__(256, 2)
input_gemm_kernel(const float* __restrict__ w0, const float* __restrict__ w1,
                  const float* __restrict__ b0, const float* __restrict__ b1)
{
    __shared__ float As[8][128];
    __shared__ float Bs[8][128];

    int dir = blockIdx.z;
    const float* Wm   = dir ? w1 : w0;
    const float* bias = dir ? b1 : b0;

    int m0 = blockIdx.y * 128;
    int n0 = blockIdx.x * 128;
    int tid = threadIdx.x;

    int arow = tid >> 1;            // 0..127
    int ak   = (tid & 1) << 2;      // 0 or 4
    int tx   = tid & 15;            // col group
    int ty   = tid >> 4;            // row group

    const float* Ap = g_emb + (size_t)(m0 + arow) * DIN + ak;
    const float* Bp = Wm    + (size_t)(n0 + arow) * DIN + ak;

    unsigned long long acc[8][4];
#pragma unroll
    for (int i = 0; i < 8; ++i)
#pragma unroll
        for (int j = 0; j < 4; ++j) acc[i][j] = 0ULL;

    float4 av = *reinterpret_cast<const float4*>(Ap);
    float4 bv = *reinterpret_cast<const float4*>(Bp);

    for (int k0 = 0; k0 < DIN; k0 += 8) {
        __syncthreads();
        As[ak + 0][arow] = av.x;  As[ak + 1][arow] = av.y;
        As[ak + 2][arow] = av.z;  As[ak + 3][arow] = av.w;
        Bs[ak + 0][arow] = bv.x;  Bs[ak + 1][arow] = bv.y;
        Bs[ak + 2][arow] = bv.z;  Bs[ak + 3][arow] = bv.w;
        __syncthreads();
        if (k0 + 8 < DIN) {     // prefetch next tile during compute
            av = *reinterpret_cast<const float4*>(Ap + k0 + 8);
            bv = *reinterpret_cast<const float4*>(Bp + k0 + 8);
        }
#pragma unroll
        for (int k = 0; k < 8; ++k) {
            float4 alo = *reinterpret_cast<const float4*>(&As[k][ty * 4]);
            float4 ahi = *reinterpret_cast<const float4*>(&As[k][64 + ty * 4]);
            ulonglong2 blo = *reinterpret_cast<const ulonglong2*>(&Bs[k][tx * 4]);
            ulonglong2 bhi = *reinterpret_cast<const ulonglong2*>(&Bs[k][64 + tx * 4]);
            unsigned long long a2[8];
            a2[0] = packdup(alo.x); a2[1] = packdup(alo.y);
            a2[2] = packdup(alo.z); a2[3] = packdup(alo.w);
            a2[4] = packdup(ahi.x); a2[5] = packdup(ahi.y);
            a2[6] = packdup(ahi.z); a2[7] = packdup(ahi.w);
#pragma unroll
            for (int i = 0; i < 8; ++i) {
                fma2(acc[i][0], a2[i], blo.x);
                fma2(acc[i][1], a2[i], blo.y);
                fma2(acc[i][2], a2[i], bhi.x);
                fma2(acc[i][3], a2[i], bhi.y);
            }
        }
    }

    float4 bz_lo = *reinterpret_cast<const float4*>(bias + n0 + tx * 4);
    float4 bz_hi = *reinterpret_cast<const float4*>(bias + n0 + 64 + tx * 4);

    float* C = g_xp + (size_t)dir * ROWS * NG;
#pragma unroll
    for (int i = 0; i < 8; ++i) {
        int m = m0 + ((i < 4) ? (ty * 4 + i) : (64 + ty * 4 + i - 4));
        float2 u0 = unpack2(acc[i][0]);
        float2 u1 = unpack2(acc[i][1]);
        float2 u2 = unpack2(acc[i][2]);
        float2 u3 = unpack2(acc[i][3]);
        float4 vlo = make_float4(u0.x + bz_lo.x, u0.y + bz_lo.y,
                                 u1.x + bz_lo.z, u1.y + bz_lo.w);
        float4 vhi = make_float4(u2.x + bz_hi.x, u2.y + bz_hi.y,
                                 u3.x + bz_hi.z, u3.y + bz_hi.w);
        *reinterpret_cast<float4*>(C + (size_t)m * NG + n0 + tx * 4)      = vlo;
        *reinterpret_cast<float4*>(C + (size_t)m * NG + n0 + 64 + tx * 4) = vhi;
    }
}

// ---------------------------------------------------------------------------
// Kernel 3: PERSISTENT bidirectional LSTM, one launch, 256 co-resident blocks.
// Co-residency is guaranteed: __launch_bounds__(256,2) caps regs at 128 and
// 48KB static smem x 2 = 96KB/SM -> 2 blocks/SM x 148 SMs = 296 >= 256.
// Block = (jt 0..31 -> 8 j-outputs => 32 gate rows; bt 0..3 -> 16 batches; dir).
// Thread (kc 0..3, jl 0..7, bg 0..7): 4 gates x 2 batches, k-chunk of 64.
//   per 4-k iter: 2 h-loads (128B/warp) + 4 w-loads (64B contig)
//   -> 32 MACs per ~6 crossbar cycles: fma2-bound, not smem-bound.
// h state K-MAJOR double buffer in global: coalesced 128B staging reads.
// kc-partials summed directly by the 128 activation threads.
// ---------------------------------------------------------------------------
__global__ void __launch_bounds__(256, 2)
lstm_persistent_kernel(const float* __restrict__ whhF,
                       const float* __restrict__ whhB,
                       float* __restrict__ out, int write_full)
{
    __shared__ ulonglong2 Wsh[64][32];   // 32 KB: [kq][r], r = gate*8 + jl
    __shared__ ulonglong2 Hsh[64][16];   // 16 KB: [kq][b]; overlaid by Psh after k-loop

    float* Psh = reinterpret_cast<float*>(Hsh);  // [kc 4][r 32][b 16] = 8 KB overlay

    int jt  = blockIdx.x;                // 0..31
    int bt  = blockIdx.y;                // 0..3
    int dir = blockIdx.z;
    int tid = threadIdx.x;
    const float* whh = dir ? whhB : whhF;

    // Stage weights once: local row r = gate*8 + jl -> whh row gate*256 + jt*8 + jl
    for (int idx = tid; idx < 32 * 64; idx += 256) {
        int r = idx >> 6, kq = idx & 63;
        int grow = ((r >> 3) << 8) + (jt << 3) + (r & 7);
        *reinterpret_cast<float4*>(&Wsh[kq][r]) =
            *reinterpret_cast<const float4*>(whh + (size_t)grow * 256 + kq * 4);
    }

    int kc = tid >> 6;                   // 0..3  k-chunk
    int jl = (tid >> 3) & 7;             // 0..7  j within block
    int bg = tid & 7;                    // 0..7  batch pair
    int b0 = bg << 1;

    // activation mapping (threads < 128)
    int jl_a = tid >> 4;                 // 0..7
    int bl_a = tid & 15;                 // 0..15
    int bg_a = (bt << 4) + bl_a;         // global batch
    int jg_a = (jt << 3) + jl_a;         // global j
    float c_reg = 0.f;

    const ulonglong2* hp = &Hsh[kc << 4][0];
    const ulonglong2* wp = &Wsh[kc << 4][0];

    for (int step = 0; step < WW; ++step) {
        int t = dir ? (WW - 1 - step) : step;
        int phase_r = step & 1;

        // prefetch xp gates (overlaps staging + k-loop)
        float x_i = 0.f, x_f = 0.f, x_g = 0.f, x_o = 0.f;
        if (tid < 128) {
            const float* xrow = g_xp + ((size_t)dir * ROWS + (size_t)bg_a * WW + t) * NG;
            x_i = __ldg(xrow + jg_a);
            x_f = __ldg(xrow + 256 + jg_a);
            x_g = __ldg(xrow + 512 + jg_a);
            x_o = __ldg(xrow + 768 + jg_a);
        }

        // stage h_prev tile: coalesced K-major reads (bypass L1: cross-SM producer)
        if (step == 0) {
            for (int idx = tid; idx < 16 * 64; idx += 256) {
                int b = idx & 15, kq = idx >> 4;
                *reinterpret_cast<float4*>(&Hsh[kq][b]) = make_float4(0.f, 0.f, 0.f, 0.f);
            }
        } else {
            const float4* hsrc = reinterpret_cast<const float4*>(&g_h2[phase_r][dir][0][0][0]);
            for (int idx = tid; idx < 16 * 64; idx += 256) {
                int b = idx & 15, kq = idx >> 4;
                *reinterpret_cast<float4*>(&Hsh[kq][b]) =
                    __ldcg(hsrc + (size_t)kq * 64 + (bt << 4) + b);
            }
        }
        __syncthreads();

        // k-loop: 16 iters of 4k; acc[gate][bj] as f32x2 pairs
        unsigned long long a00 = 0ULL, a01 = 0ULL, a10 = 0ULL, a11 = 0ULL;
        unsigned long long a20 = 0ULL, a21 = 0ULL, a30 = 0ULL, a31 = 0ULL;
#pragma unroll
        for (int i = 0; i < 16; ++i) {
            ulonglong2 h0 = hp[(i << 4) + b0];
            ulonglong2 h1 = hp[(i << 4) + b0 + 1];
            ulonglong2 w0 = wp[(i << 5) + jl];        // gate 0 row
            ulonglong2 w1 = wp[(i << 5) + 8 + jl];    // gate 1
            ulonglong2 w2 = wp[(i << 5) + 16 + jl];   // gate 2
            ulonglong2 w3 = wp[(i << 5) + 24 + jl];   // gate 3
            fma2(a00, w0.x, h0.x); fma2(a00, w0.y, h0.y);
            fma2(a01, w0.x, h1.x); fma2(a01, w0.y, h1.y);
            fma2(a10, w1.x, h0.x); fma2(a10, w1.y, h0.y);
            fma2(a11, w1.x, h1.x); fma2(a11, w1.y, h1.y);
            fma2(a20, w2.x, h0.x); fma2(a20, w2.y, h0.y);
            fma2(a21, w2.x, h1.x); fma2(a21, w2.y, h1.y);
            fma2(a30, w3.x, h0.x); fma2(a30, w3.y, h0.y);
            fma2(a31, w3.x, h1.x); fma2(a31, w3.y, h1.y);
        }
        __syncthreads();   // all Hsh reads done; safe to overlay with Psh

        // write kc-partials: Psh[kc][gate*8+jl][b]
        {
            float2 u;
            int base = (kc << 9) + jl * 16;
            u = unpack2(a00); Psh[base + ( 0 << 4) + b0]     = u.x + u.y;
            u = unpack2(a01); Psh[base + ( 0 << 4) + b0 + 1] = u.x + u.y;
            u = unpack2(a10); Psh[base + ( 8 << 4) + b0]     = u.x + u.y;
            u = unpack2(a11); Psh[base + ( 8 << 4) + b0 + 1] = u.x + u.y;
            u = unpack2(a20); Psh[base + (16 << 4) + b0]     = u.x + u.y;
            u = unpack2(a21); Psh[base + (16 << 4) + b0 + 1] = u.x + u.y;
            u = unpack2(a30); Psh[base + (24 << 4) + b0]     = u.x + u.y;
            u = unpack2(a31); Psh[base + (24 << 4) + b0 + 1] = u.x + u.y;
        }
        __syncthreads();

        // activation: sum 4 kc-partials per gate, apply LSTM cell
        if (tid < 128) {
            int o = jl_a * 16 + bl_a;
            float gi = x_i, gf = x_f, gg = x_g, go = x_o;
#pragma unroll
            for (int k = 0; k < 4; ++k) {
                int base = (k << 9) + o;
                gi += Psh[base];
                gf += Psh[base + (8 << 4)];
                gg += Psh[base + (16 << 4)];
                go += Psh[base + (24 << 4)];
            }
            float ig = 1.f / (1.f + expf(-gi));
            float fg = 1.f / (1.f + expf(-gf));
            float tg = tanhf(gg);
            float og = 1.f / (1.f + expf(-go));
            c_reg = fg * c_reg + ig * tg;
            float h = og * tanhf(c_reg);

            g_h2[phase_r ^ 1][dir][jg_a >> 2][bg_a][jg_a & 3] = h;
            size_t bw = (size_t)bg_a * WW + t;
            out[bw * 512 + (dir << 8) + jg_a] = h;
            if (write_full)
                out[OUT_RNN1_SZ + (size_t)dir * OUT_H_SZ + bw * HH + jg_a] = h;
        }

        // grid barrier (skip after final step)
        if (step < WW - 1) {
            __threadfence();
            __syncthreads();
            if (tid == 0) {
                atomicAdd(&g_bar, 1u);
                unsigned target = (unsigned)(step + 1) * NBLK;
                while (*reinterpret_cast<volatile unsigned*>(&g_bar) < target) { }
            }
            __syncthreads();
        }
    }
}

// ---------------------------------------------------------------------------
extern "C" void kernel_launch(void* const* d_in, const int* in_sizes, int n_in,
                              void* d_out, int out_size)
{
    const int*   words      = (const int*)  d_in[0];
    const float* features   = (const float*)d_in[1];
    const int*   lip        = (const int*)  d_in[2];
    const int*   postags    = (const int*)  d_in[3];
    // d_in[4] = chars (unused), d_in[5] = masks (unused)
    const float* word_table = (const float*)d_in[6];
    const float* pos_table  = (const float*)d_in[7];
    const float* w_ih_f     = (const float*)d_in[8];
    const float* w_hh_f     = (const float*)d_in[9];
    const float* b_f        = (const float*)d_in[10];
    const float* w_ih_b     = (const float*)d_in[11];
    const float* w_hh_b     = (const float*)d_in[12];
    const float* b_b        = (const float*)d_in[13];
    float* out = (float*)d_out;

    int write_full = ((size_t)out_size >= OUT_TOTAL) ? 1 : 0;

    // Phase 1: embeddings (+ barrier reset)
    embed_kernel<<<ROWS, 128>>>(words, features, lip, postags, word_table, pos_table);

    // Phase 2: input projections, f32x2 GEMM
    input_gemm_kernel<<<dim3(8, 127, 2), 256>>>(w_ih_f, w_ih_b, b_f, b_b);

    // Phase 3: persistent recurrence, single launch
    lstm_persistent_kernel<<<dim3(32, 4, 2), 256>>>(w_hh_f, w_hh_b, out, write_full);
}

// round 7
// speedup vs baseline: 1.9176x; 1.1634x over previous
#include <cuda_runtime.h>
#include <cuda_bf16.h>
#include <math.h>
#include <stdint.h>

// Problem constants
#define BB    64
#define WW    254
#define SS    256
#define DPHO  768
#define DIN   968          // 100 + 768 + 100
#define KP    1024         // K padded
#define HH    256
#define NG    1024         // 4*H
#define ROWS  (BB*WW)      // 16256 = 127*128
#define NBLK  256          // persistent LSTM grid size

// Output layout: rnn1_out [B,W,512] | hf [B,W,256] | hb [B,W,256]
#define OUT_RNN1_SZ  ((size_t)ROWS * 512)
#define OUT_H_SZ     ((size_t)ROWS * HH)
#define OUT_TOTAL    (OUT_RNN1_SZ + 2*OUT_H_SZ)

// Scratch (__device__ globals; 16B-aligned for vector/cp.async access)
__device__ alignas(256) __nv_bfloat16 g_ehi[(size_t)ROWS * KP];
__device__ alignas(256) __nv_bfloat16 g_elo[(size_t)ROWS * KP];
__device__ alignas(256) __nv_bfloat16 g_whi[2][(size_t)NG * KP];
__device__ alignas(256) __nv_bfloat16 g_wlo[2][(size_t)NG * KP];
// xp in [dir][w][gate*256+j][b] layout: coalesced epilogue AND LSTM reads
__device__ alignas(256) float g_xp2[2][WW][4][256][64];
// h state double-buffered, K-MAJOR: [phase][dir][kq=64][b=64][ki=4]
__device__ alignas(256) float g_h2[2][2][64][64][4];
__device__ unsigned g_bar;

// ---- packed f32x2 helpers (LSTM inner loop) ----
__device__ __forceinline__ void fma2(unsigned long long& acc,
                                     unsigned long long a, unsigned long long b) {
    asm("fma.rn.f32x2 %0, %1, %2, %0;" : "+l"(acc) : "l"(a), "l"(b));
}
__device__ __forceinline__ float2 unpack2(unsigned long long v) {
    float2 f;
    asm("mov.b64 {%0, %1}, %2;" : "=f"(f.x), "=f"(f.y) : "l"(v));
    return f;
}

// ---- baseline-ISA tensor-core helpers (sm_80+: valid on plain sm_100) ----
__device__ __forceinline__ uint32_t smem_u32(const void* p) {
    return (uint32_t)__cvta_generic_to_shared(p);
}
__device__ __forceinline__ void ldsm4(uint32_t* r, uint32_t addr) {
    asm volatile("ldmatrix.sync.aligned.m8n8.x4.shared.b16 {%0,%1,%2,%3}, [%4];"
                 : "=r"(r[0]), "=r"(r[1]), "=r"(r[2]), "=r"(r[3]) : "r"(addr));
}
__device__ __forceinline__ void mma16816(float* d, const uint32_t* a,
                                         uint32_t b0, uint32_t b1) {
    asm volatile("mma.sync.aligned.m16n8k16.row.col.f32.bf16.bf16.f32 "
                 "{%0,%1,%2,%3}, {%4,%5,%6,%7}, {%8,%9}, {%0,%1,%2,%3};"
                 : "+f"(d[0]), "+f"(d[1]), "+f"(d[2]), "+f"(d[3])
                 : "r"(a[0]), "r"(a[1]), "r"(a[2]), "r"(a[3]), "r"(b0), "r"(b1));
}
__device__ __forceinline__ void cpasync16(uint32_t dst, const void* src) {
    asm volatile("cp.async.cg.shared.global [%0], [%1], 16;" :: "r"(dst), "l"(src));
}

// ---------------------------------------------------------------------------
// Kernel 1: emb row m = w*64 + b, split into bf16 hi/lo, zero-padded to KP.
// searchsorted-right segment semantics == interval sum [lip[w], lip[w+1]).
// Also resets the persistent-kernel grid barrier.
// ---------------------------------------------------------------------------
__global__ void embed_kernel(const int* __restrict__ words,
                             const float* __restrict__ features,
                             const int* __restrict__ lip,
                             const int* __restrict__ postags,
                             const float* __restrict__ word_table,
                             const float* __restrict__ pos_table)
{
    if (blockIdx.x == 0 && threadIdx.x == 0) g_bar = 0;

    int bw = blockIdx.x;            // b*WW + w
    int b  = bw / WW;
    int w  = bw - b * WW;
    int tid = threadIdx.x;          // 128 threads
    size_t m = (size_t)w * 64 + b;  // W-MAJOR row

    int wid = words[bw];
    int pid = postags[bw];
    int s0 = lip[b * (WW + 2) + w];
    int s1 = lip[b * (WW + 2) + w + 1];
    if (s1 > SS) s1 = SS;
    if (s0 < 0)  s0 = 0;

    for (int d = tid; d < KP; d += 128) {
        float v = 0.f;
        if (d < 100) {
            v = word_table[wid * 100 + d];
        } else if (d < 868) {
            float acc = 0.f;
            for (int t = s0; t < s1; ++t)
                acc += features[((size_t)b * SS + t) * DPHO + (d - 100)];
            v = acc;
        } else if (d < 968) {
            v = pos_table[pid * 100 + (d - 868)];
        }
        __nv_bfloat16 hi = __float2bfloat16(v);
        g_ehi[m * KP + d] = hi;
        g_elo[m * KP + d] = __float2bfloat16(v - __bfloat162float(hi));
    }
}

// ---------------------------------------------------------------------------
// Kernel 1b: split w_ih into bf16 hi/lo, zero-padded to KP. grid (1024, 2).
// ---------------------------------------------------------------------------
__global__ void prep_w_kernel(const float* __restrict__ wf,
                              const float* __restrict__ wb)
{
    int r   = blockIdx.x;
    int dir = blockIdx.y;
    int tid = threadIdx.x;
    const float* src = (dir ? wb : wf) + (size_t)r * DIN;
    for (int d = tid; d < KP; d += 128) {
        float v = (d < DIN) ? src[d] : 0.f;
        __nv_bfloat16 hi = __float2bfloat16(v);
        g_whi[dir][(size_t)r * KP + d] = hi;
        g_wlo[dir][(size_t)r * KP + d] = __float2bfloat16(v - __bfloat162float(hi));
    }
}

// ---------------------------------------------------------------------------
// Kernel 2: input projection on TENSOR CORES via mma.sync (bf16, 3-term split).
// K' = 3*1024: seg0 ehi*whi, seg1 elo*whi, seg2 ehi*wlo (lo*lo dropped).
// 128x128 tile, BK=32, 256 thr, 8 warps (2M x 4N), warp = 64x32.
// SMEM rows at 80B stride: 16B aligned, conflict-free ldmatrix (5r mod 8 perm).
// Double-buffered cp.async (96 stages). Epilogue via transposed smem tile
// -> coalesced stores into g_xp2[dir][w][n][b], bias fused.
// ---------------------------------------------------------------------------
#define STG_A   10240                    // 128 rows * 80B
#define STG_TOT 20480                    // A + B per stage

__global__ void __launch_bounds__(256)
tc_gemm_kernel(const float* __restrict__ b0p, const float* __restrict__ b1p)
{
    __shared__ alignas(128) char sbuf[2 * STG_TOT];   // 40 KB

    int nt = blockIdx.x, mt = blockIdx.y, dir = blockIdx.z;
    int tid = threadIdx.x;
    int wid = tid >> 5, lane = tid & 31;
    int wm = wid & 1, wn = wid >> 1;
    int m0 = mt * 128, n0 = nt * 128;
    const float* bias = dir ? b1p : b0p;

    const __nv_bfloat16* Asrc[3] = { g_ehi + (size_t)m0 * KP,
                                     g_elo + (size_t)m0 * KP,
                                     g_ehi + (size_t)m0 * KP };
    const __nv_bfloat16* Bsrc[3] = { g_whi[dir] + (size_t)n0 * KP,
                                     g_whi[dir] + (size_t)n0 * KP,
                                     g_wlo[dir] + (size_t)n0 * KP };

    float acc[4][4][4];
#pragma unroll
    for (int i = 0; i < 4; ++i)
#pragma unroll
        for (int j = 0; j < 4; ++j)
#pragma unroll
            for (int q = 0; q < 4; ++q) acc[i][j][q] = 0.f;

    // ldmatrix source addresses (fixed per thread, per buffer)
    int arow = wm * 64 + (lane & 15);
    int brow = wn * 32 + (lane & 15);
    int kld  = (lane >> 4) * 16;

    // staging indices: thread covers A chunks {tid, tid+256}, B same
    int r0s = tid >> 2,        c0s = tid & 3;
    int r1s = (tid + 256) >> 2, c1s = (tid + 256) & 3;

    // ---- preload stage 0 ----
    {
        const __nv_bfloat16* A = Asrc[0];
        const __nv_bfloat16* B = Bsrc[0];
        char* sa = sbuf; char* sb = sbuf + STG_A;
        cpasync16(smem_u32(sa + r0s * 80 + c0s * 16), A + (size_t)r0s * KP + c0s * 8);
        cpasync16(smem_u32(sa + r1s * 80 + c1s * 16), A + (size_t)r1s * KP + c1s * 8);
        cpasync16(smem_u32(sb + r0s * 80 + c0s * 16), B + (size_t)r0s * KP + c0s * 8);
        cpasync16(smem_u32(sb + r1s * 80 + c1s * 16), B + (size_t)r1s * KP + c1s * 8);
        asm volatile("cp.async.commit_group;");
    }

    for (int s = 0; s < 96; ++s) {
        if (s + 1 < 96) {
            int seg = (s + 1) >> 5, kk = ((s + 1) & 31) << 5;
            const __nv_bfloat16* A = Asrc[seg];
            const __nv_bfloat16* B = Bsrc[seg];
            char* sa = sbuf + ((s + 1) & 1) * STG_TOT;
            char* sb = sa + STG_A;
            cpasync16(smem_u32(sa + r0s * 80 + c0s * 16), A + (size_t)r0s * KP + kk + c0s * 8);
            cpasync16(smem_u32(sa + r1s * 80 + c1s * 16), A + (size_t)r1s * KP + kk + c1s * 8);
            cpasync16(smem_u32(sb + r0s * 80 + c0s * 16), B + (size_t)r0s * KP + kk + c0s * 8);
            cpasync16(smem_u32(sb + r1s * 80 + c1s * 16), B + (size_t)r1s * KP + kk + c1s * 8);
            asm volatile("cp.async.commit_group;");
            asm volatile("cp.async.wait_group 1;");
        } else {
            asm volatile("cp.async.wait_group 0;");
        }
        __syncthreads();

        uint32_t abase = smem_u32(sbuf + (s & 1) * STG_TOT);
        uint32_t bbase = abase + STG_A;
#pragma unroll
        for (int j = 0; j < 2; ++j) {
            int kb = j * 32 + kld;
            uint32_t af[4][4], bf[2][4];
#pragma unroll
            for (int mi = 0; mi < 4; ++mi)
                ldsm4(af[mi], abase + (arow + mi * 16) * 80 + kb);
#pragma unroll
            for (int g = 0; g < 2; ++g)
                ldsm4(bf[g], bbase + (brow + g * 16) * 80 + kb);
#pragma unroll
            for (int mi = 0; mi < 4; ++mi) {
#pragma unroll
                for (int ni = 0; ni < 4; ++ni) {
                    int g = ni >> 1;
                    uint32_t bb0 = (ni & 1) ? bf[g][1] : bf[g][0];
                    uint32_t bb1 = (ni & 1) ? bf[g][3] : bf[g][2];
                    mma16816(acc[mi][ni], af[mi], bb0, bb1);
                }
            }
        }
        __syncthreads();
    }

    // ---- epilogue: 4 n-chunks of 32 via transposed smem tile [32][132] ----
    float* smemT = reinterpret_cast<float*>(sbuf);
    for (int c = 0; c < 4; ++c) {
        if (wn == c) {
#pragma unroll
            for (int mi = 0; mi < 4; ++mi)
#pragma unroll
                for (int ni = 0; ni < 4; ++ni) {
                    int nn = ni * 8 + (lane & 3) * 2;
                    int m  = wm * 64 + mi * 16 + (lane >> 2);
                    smemT[nn * 132 + m]           = acc[mi][ni][0];
                    smemT[(nn + 1) * 132 + m]     = acc[mi][ni][1];
                    smemT[nn * 132 + m + 8]       = acc[mi][ni][2];
                    smemT[(nn + 1) * 132 + m + 8] = acc[mi][ni][3];
                }
        }
        __syncthreads();

        int nloc = tid >> 3, grp = tid & 7;
        int n_g = n0 + c * 32 + nloc;
        float bz = __ldg(bias + n_g);
#pragma unroll
        for (int q = 0; q < 4; ++q) {
            int m = grp * 16 + q * 4;
            float4 v = *reinterpret_cast<const float4*>(&smemT[nloc * 132 + m]);
            v.x += bz; v.y += bz; v.z += bz; v.w += bz;
            int mg = m0 + m, wq = mg >> 6, bq = mg & 63;
            float* dst = reinterpret_cast<float*>(g_xp2) +
                         (((size_t)dir * WW + wq) * 1024 + n_g) * 64 + bq;
            *reinterpret_cast<float4*>(dst) = v;
        }
        __syncthreads();
    }
}

// ---------------------------------------------------------------------------
// Kernel 3: PERSISTENT bidirectional LSTM (structure from round 5 PASS; xp
// reads follow [dir][w][gate][j][b] layout, fully coalesced).
// ---------------------------------------------------------------------------
__global__ void __launch_bounds__(256, 2)
lstm_persistent_kernel(const float* __restrict__ whhF,
                       const float* __restrict__ whhB,
                       float* __restrict__ out, int write_full)
{
    __shared__ ulonglong2 Wsh[64][32];   // 32 KB: [kq][r], r = gate*8 + jl
    __shared__ ulonglong2 Hsh[64][16];   // 16 KB: [kq][b]; overlaid by Psh

    float* Psh = reinterpret_cast<float*>(Hsh);  // [kc 4][r 32][b 16]

    int jt  = blockIdx.x;                // 0..31
    int bt  = blockIdx.y;                // 0..3
    int dir = blockIdx.z;
    int tid = threadIdx.x;
    const float* whh = dir ? whhB : whhF;

    for (int idx = tid; idx < 32 * 64; idx += 256) {
        int r = idx >> 6, kq = idx & 63;
        int grow = ((r >> 3) << 8) + (jt << 3) + (r & 7);
        *reinterpret_cast<float4*>(&Wsh[kq][r]) =
            *reinterpret_cast<const float4*>(whh + (size_t)grow * 256 + kq * 4);
    }

    int kc = tid >> 6;                   // 0..3
    int jl = (tid >> 3) & 7;             // 0..7
    int bg = tid & 7;                    // 0..7
    int b0 = bg << 1;

    int jl_a = tid >> 4;                 // 0..7
    int bl_a = tid & 15;                 // 0..15
    int bg_a = (bt << 4) + bl_a;
    int jg_a = (jt << 3) + jl_a;
    float c_reg = 0.f;

    const ulonglong2* hp = &Hsh[kc << 4][0];
    const ulonglong2* wp = &Wsh[kc << 4][0];

    for (int step = 0; step < WW; ++step) {
        int t = dir ? (WW - 1 - step) : step;
        int phase_r = step & 1;

        float x_i = 0.f, x_f = 0.f, x_g = 0.f, x_o = 0.f;
        if (tid < 128) {
            const float* xb = &g_xp2[dir][t][0][jg_a][bg_a];
            x_i = __ldg(xb);
            x_f = __ldg(xb + 1 * 256 * 64);
            x_g = __ldg(xb + 2 * 256 * 64);
            x_o = __ldg(xb + 3 * 256 * 64);
        }

        if (step == 0) {
            for (int idx = tid; idx < 16 * 64; idx += 256) {
                int b = idx & 15, kq = idx >> 4;
                *reinterpret_cast<float4*>(&Hsh[kq][b]) = make_float4(0.f, 0.f, 0.f, 0.f);
            }
        } else {
            const float4* hsrc = reinterpret_cast<const float4*>(&g_h2[phase_r][dir][0][0][0]);
            for (int idx = tid; idx < 16 * 64; idx += 256) {
                int b = idx & 15, kq = idx >> 4;
                *reinterpret_cast<float4*>(&Hsh[kq][b]) =
                    __ldcg(hsrc + (size_t)kq * 64 + (bt << 4) + b);
            }
        }
        __syncthreads();

        unsigned long long a00 = 0ULL, a01 = 0ULL, a10 = 0ULL, a11 = 0ULL;
        unsigned long long a20 = 0ULL, a21 = 0ULL, a30 = 0ULL, a31 = 0ULL;
#pragma unroll
        for (int i = 0; i < 16; ++i) {
            ulonglong2 h0 = hp[(i << 4) + b0];
            ulonglong2 h1 = hp[(i << 4) + b0 + 1];
            ulonglong2 w0 = wp[(i << 5) + jl];
            ulonglong2 w1 = wp[(i << 5) + 8 + jl];
            ulonglong2 w2 = wp[(i << 5) + 16 + jl];
            ulonglong2 w3 = wp[(i << 5) + 24 + jl];
            fma2(a00, w0.x, h0.x); fma2(a00, w0.y, h0.y);
            fma2(a01, w0.x, h1.x); fma2(a01, w0.y, h1.y);
            fma2(a10, w1.x, h0.x); fma2(a10, w1.y, h0.y);
            fma2(a11, w1.x, h1.x); fma2(a11, w1.y, h1.y);
            fma2(a20, w2.x, h0.x); fma2(a20, w2.y, h0.y);
            fma2(a21, w2.x, h1.x); fma2(a21, w2.y, h1.y);
            fma2(a30, w3.x, h0.x); fma2(a30, w3.y, h0.y);
            fma2(a31, w3.x, h1.x); fma2(a31, w3.y, h1.y);
        }
        __syncthreads();

        {
            float2 u;
            int base = (kc << 9) + jl * 16;
            u = unpack2(a00); Psh[base + ( 0 << 4) + b0]     = u.x + u.y;
            u = unpack2(a01); Psh[base + ( 0 << 4) + b0 + 1] = u.x + u.y;
            u = unpack2(a10); Psh[base + ( 8 << 4) + b0]     = u.x + u.y;
            u = unpack2(a11); Psh[base + ( 8 << 4) + b0 + 1] = u.x + u.y;
            u = unpack2(a20); Psh[base + (16 << 4) + b0]     = u.x + u.y;
            u = unpack2(a21); Psh[base + (16 << 4) + b0 + 1] = u.x + u.y;
            u = unpack2(a30); Psh[base + (24 << 4) + b0]     = u.x + u.y;
            u = unpack2(a31); Psh[base + (24 << 4) + b0 + 1] = u.x + u.y;
        }
        __syncthreads();

        if (tid < 128) {
            int o = jl_a * 16 + bl_a;
            float gi = x_i, gf = x_f, gg = x_g, go = x_o;
#pragma unroll
            for (int k = 0; k < 4; ++k) {
                int base = (k << 9) + o;
                gi += Psh[base];
                gf += Psh[base + (8 << 4)];
                gg += Psh[base + (16 << 4)];
                go += Psh[base + (24 << 4)];
            }
            float ig = 1.f / (1.f + expf(-gi));
            float fg = 1.f / (1.f + expf(-gf));
            float tg = tanhf(gg);
            float og = 1.f / (1.f + expf(-go));
            c_reg = fg * c_reg + ig * tg;
            float h = og * tanhf(c_reg);

            g_h2[phase_r ^ 1][dir][jg_a >> 2][bg_a][jg_a & 3] = h;
            size_t bw = (size_t)bg_a * WW + t;
            out[bw * 512 + (dir << 8) + jg_a] = h;
            if (write_full)
                out[OUT_RNN1_SZ + (size_t)dir * OUT_H_SZ + bw * HH + jg_a] = h;
        }

        if (step < WW - 1) {
            __threadfence();
            __syncthreads();
            if (tid == 0) {
                atomicAdd(&g_bar, 1u);
                unsigned target = (unsigned)(step + 1) * NBLK;
                while (*reinterpret_cast<volatile unsigned*>(&g_bar) < target) { }
            }
            __syncthreads();
        }
    }
}

// ---------------------------------------------------------------------------
extern "C" void kernel_launch(void* const* d_in, const int* in_sizes, int n_in,
                              void* d_out, int out_size)
{
    const int*   words      = (const int*)  d_in[0];
    const float* features   = (const float*)d_in[1];
    const int*   lip        = (const int*)  d_in[2];
    const int*   postags    = (const int*)  d_in[3];
    // d_in[4] = chars (unused), d_in[5] = masks (unused)
    const float* word_table = (const float*)d_in[6];
    const float* pos_table  = (const float*)d_in[7];
    const float* w_ih_f     = (const float*)d_in[8];
    const float* w_hh_f     = (const float*)d_in[9];
    const float* b_f        = (const float*)d_in[10];
    const float* w_ih_b     = (const float*)d_in[11];
    const float* w_hh_b     = (const float*)d_in[12];
    const float* b_b        = (const float*)d_in[13];
    float* out = (float*)d_out;

    int write_full = ((size_t)out_size >= OUT_TOTAL) ? 1 : 0;

    // Phase 1: embeddings (bf16 hi/lo split) + weight split + barrier reset
    embed_kernel<<<ROWS, 128>>>(words, features, lip, postags, word_table, pos_table);
    prep_w_kernel<<<dim3(NG, 2), 128>>>(w_ih_f, w_ih_b);

    // Phase 2: input projections on tensor cores (mma.sync bf16 split)
    tc_gemm_kernel<<<dim3(8, 127, 2), 256>>>(b_f, b_b);

    // Phase 3: persistent recurrence, single launch
    lstm_persistent_kernel<<<dim3(32, 4, 2), 256>>>(w_hh_f, w_hh_b, out, write_full);
}

// round 9
// speedup vs baseline: 2.0788x; 1.0840x over previous
#include <cuda_runtime.h>
#include <cuda_bf16.h>
#include <math.h>
#include <stdint.h>

// Problem constants
#define BB    64
#define WW    254
#define SS    256
#define DPHO  768
#define DIN   968          // 100 + 768 + 100
#define KP    1024         // K padded
#define HH    256
#define NG    1024         // 4*H
#define ROWS  (BB*WW)      // 16256 = 127*128

// Output layout: rnn1_out [B,W,512] | hf [B,W,256] | hb [B,W,256]
#define OUT_RNN1_SZ  ((size_t)ROWS * 512)
#define OUT_H_SZ     ((size_t)ROWS * HH)
#define OUT_TOTAL    (OUT_RNN1_SZ + 2*OUT_H_SZ)

// Scratch (__device__ globals; 16B-aligned for vector/cp.async access)
__device__ alignas(256) __nv_bfloat16 g_ehi[(size_t)ROWS * KP];
__device__ alignas(256) __nv_bfloat16 g_elo[(size_t)ROWS * KP];
__device__ alignas(256) __nv_bfloat16 g_whi[2][(size_t)NG * KP];
__device__ alignas(256) __nv_bfloat16 g_wlo[2][(size_t)NG * KP];
// xp in [dir][w][gate*256+j][b] layout: coalesced epilogue AND LSTM reads
__device__ alignas(256) float g_xp2[2][WW][4][256][64];
// h state double-buffered, K-MAJOR: [phase][dir][kq=64][b=64][ki=4]
__device__ alignas(256) float g_h2[2][2][64][64][4];
__device__ unsigned g_barD[2];       // per-direction barrier counters

// ---- packed f32x2 helpers (LSTM inner loop) ----
__device__ __forceinline__ void fma2(unsigned long long& acc,
                                     unsigned long long a, unsigned long long b) {
    asm("fma.rn.f32x2 %0, %1, %2, %0;" : "+l"(acc) : "l"(a), "l"(b));
}
__device__ __forceinline__ float2 unpack2(unsigned long long v) {
    float2 f;
    asm("mov.b64 {%0, %1}, %2;" : "=f"(f.x), "=f"(f.y) : "l"(v));
    return f;
}

// ---- baseline-ISA tensor-core helpers (sm_80+: valid on plain sm_100) ----
__device__ __forceinline__ uint32_t smem_u32(const void* p) {
    return (uint32_t)__cvta_generic_to_shared(p);
}
__device__ __forceinline__ void ldsm4(uint32_t* r, uint32_t addr) {
    asm volatile("ldmatrix.sync.aligned.m8n8.x4.shared.b16 {%0,%1,%2,%3}, [%4];"
                 : "=r"(r[0]), "=r"(r[1]), "=r"(r[2]), "=r"(r[3]) : "r"(addr));
}
__device__ __forceinline__ void mma16816(float* d, const uint32_t* a,
                                         uint32_t b0, uint32_t b1) {
    asm volatile("mma.sync.aligned.m16n8k16.row.col.f32.bf16.bf16.f32 "
                 "{%0,%1,%2,%3}, {%4,%5,%6,%7}, {%8,%9}, {%0,%1,%2,%3};"
                 : "+f"(d[0]), "+f"(d[1]), "+f"(d[2]), "+f"(d[3])
                 : "r"(a[0]), "r"(a[1]), "r"(a[2]), "r"(a[3]), "r"(b0), "r"(b1));
}
__device__ __forceinline__ void cpasync16(uint32_t dst, const void* src) {
    asm volatile("cp.async.cg.shared.global [%0], [%1], 16;" :: "r"(dst), "l"(src));
}

// ---------------------------------------------------------------------------
// Kernel 1: emb row m = w*64 + b, split into bf16 hi/lo, zero-padded to KP.
// searchsorted-right segment semantics == interval sum [lip[w], lip[w+1]).
// Also resets the persistent-kernel barrier counters.
// ---------------------------------------------------------------------------
__global__ void embed_kernel(const int* __restrict__ words,
                             const float* __restrict__ features,
                             const int* __restrict__ lip,
                             const int* __restrict__ postags,
                             const float* __restrict__ word_table,
                             const float* __restrict__ pos_table)
{
    if (blockIdx.x == 0 && threadIdx.x == 0) { g_barD[0] = 0; g_barD[1] = 0; }

    int bw = blockIdx.x;            // b*WW + w
    int b  = bw / WW;
    int w  = bw - b * WW;
    int tid = threadIdx.x;          // 128 threads
    size_t m = (size_t)w * 64 + b;  // W-MAJOR row

    int wid = words[bw];
    int pid = postags[bw];
    int s0 = lip[b * (WW + 2) + w];
    int s1 = lip[b * (WW + 2) + w + 1];
    if (s1 > SS) s1 = SS;
    if (s0 < 0)  s0 = 0;

    for (int d = tid; d < KP; d += 128) {
        float v = 0.f;
        if (d < 100) {
            v = word_table[wid * 100 + d];
        } else if (d < 868) {
            float acc = 0.f;
            for (int t = s0; t < s1; ++t)
                acc += features[((size_t)b * SS + t) * DPHO + (d - 100)];
            v = acc;
        } else if (d < 968) {
            v = pos_table[pid * 100 + (d - 868)];
        }
        __nv_bfloat16 hi = __float2bfloat16(v);
        g_ehi[m * KP + d] = hi;
        g_elo[m * KP + d] = __float2bfloat16(v - __bfloat162float(hi));
    }
}

// ---------------------------------------------------------------------------
// Kernel 1b: split w_ih into bf16 hi/lo, zero-padded to KP. grid (1024, 2).
// ---------------------------------------------------------------------------
__global__ void prep_w_kernel(const float* __restrict__ wf,
                              const float* __restrict__ wb)
{
    int r   = blockIdx.x;
    int dir = blockIdx.y;
    int tid = threadIdx.x;
    const float* src = (dir ? wb : wf) + (size_t)r * DIN;
    for (int d = tid; d < KP; d += 128) {
        float v = (d < DIN) ? src[d] : 0.f;
        __nv_bfloat16 hi = __float2bfloat16(v);
        g_whi[dir][(size_t)r * KP + d] = hi;
        g_wlo[dir][(size_t)r * KP + d] = __float2bfloat16(v - __bfloat162float(hi));
    }
}

// ---------------------------------------------------------------------------
// Kernel 2: input projection via mma.sync (bf16, 3-term split, K'=3*1024).
// 128x128 tile, BK=64, 48 stages, 3-stage cp.async ring with prefetch
// distance 2 and ONE __syncthreads per stage:
//   iter s: wait_group(1)  -> stage s resident (s+1 may be in flight)
//           __syncthreads  -> all threads done computing stage s-1
//           issue stage s+2 (targets buf (s+2)%3 == (s-1)%3: safe)
//           compute stage s (4 k16-blocks, 64 mma/warp)
// SMEM rows at 144B stride (16B aligned). 108KB dynamic smem.
// Epilogue via transposed smem tile -> coalesced g_xp2 stores, bias fused.
// ---------------------------------------------------------------------------
#define ROWB    144                      // bytes per smem row (128 data + 16 pad)
#define STG_A   (128 * ROWB)             // 18432
#define STG_TOT (2 * STG_A)              // 36864
#define SMEM_GEMM (3 * STG_TOT)          // 110592

__global__ void __launch_bounds__(256)
tc_gemm_kernel(const float* __restrict__ b0p, const float* __restrict__ b1p)
{
    extern __shared__ char dynbuf[];

    int nt = blockIdx.x, mt = blockIdx.y, dir = blockIdx.z;
    int tid = threadIdx.x;
    int wid = tid >> 5, lane = tid & 31;
    int wm = wid & 1, wn = wid >> 1;
    int m0 = mt * 128, n0 = nt * 128;
    const float* bias = dir ? b1p : b0p;

    const __nv_bfloat16* Asrc[3] = { g_ehi + (size_t)m0 * KP,
                                     g_elo + (size_t)m0 * KP,
                                     g_ehi + (size_t)m0 * KP };
    const __nv_bfloat16* Bsrc[3] = { g_whi[dir] + (size_t)n0 * KP,
                                     g_whi[dir] + (size_t)n0 * KP,
                                     g_wlo[dir] + (size_t)n0 * KP };

    float acc[4][4][4];
#pragma unroll
    for (int i = 0; i < 4; ++i)
#pragma unroll
        for (int j = 0; j < 4; ++j)
#pragma unroll
            for (int q = 0; q < 4; ++q) acc[i][j][q] = 0.f;

    int arow = wm * 64 + (lane & 15);
    int brow = wn * 32 + (lane & 15);
    int kld  = (lane >> 4) * 16;

    // stage loader: 1024 16B chunks per operand, 4 per thread per operand
    auto stage_load = [&](int s) {
        int seg = s >> 4, kk = (s & 15) << 6;     // 64 elements per stage
        const __nv_bfloat16* A = Asrc[seg];
        const __nv_bfloat16* B = Bsrc[seg];
        char* sa = dynbuf + (s % 3) * STG_TOT;
        char* sb = sa + STG_A;
#pragma unroll
        for (int i = 0; i < 4; ++i) {
            int idx = tid + i * 256;
            int r = idx >> 3, c = idx & 7;
            cpasync16(smem_u32(sa + r * ROWB + c * 16),
                      A + (size_t)r * KP + kk + c * 8);
            cpasync16(smem_u32(sb + r * ROWB + c * 16),
                      B + (size_t)r * KP + kk + c * 8);
        }
    };

    stage_load(0); asm volatile("cp.async.commit_group;");
    stage_load(1); asm volatile("cp.async.commit_group;");

    for (int s = 0; s < 48; ++s) {
        asm volatile("cp.async.wait_group 1;");
        __syncthreads();
        if (s + 2 < 48) stage_load(s + 2);
        asm volatile("cp.async.commit_group;");

        uint32_t abase = smem_u32(dynbuf + (s % 3) * STG_TOT);
        uint32_t bbase = abase + STG_A;
#pragma unroll
        for (int j = 0; j < 4; ++j) {
            int kb = j * 32 + kld;
            uint32_t af[4][4], bf[2][4];
#pragma unroll
            for (int mi = 0; mi < 4; ++mi)
                ldsm4(af[mi], abase + (arow + mi * 16) * ROWB + kb);
#pragma unroll
            for (int g = 0; g < 2; ++g)
                ldsm4(bf[g], bbase + (brow + g * 16) * ROWB + kb);
#pragma unroll
            for (int mi = 0; mi < 4; ++mi) {
#pragma unroll
                for (int ni = 0; ni < 4; ++ni) {
                    int g = ni >> 1;
                    uint32_t bb0 = (ni & 1) ? bf[g][1] : bf[g][0];
                    uint32_t bb1 = (ni & 1) ? bf[g][3] : bf[g][2];
                    mma16816(acc[mi][ni], af[mi], bb0, bb1);
                }
            }
        }
    }
    __syncthreads();

    // ---- epilogue: 4 n-chunks of 32 via transposed smem tile [32][132] ----
    float* smemT = reinterpret_cast<float*>(dynbuf);
    for (int c = 0; c < 4; ++c) {
        if (wn == c) {
#pragma unroll
            for (int mi = 0; mi < 4; ++mi)
#pragma unroll
                for (int ni = 0; ni < 4; ++ni) {
                    int nn = ni * 8 + (lane & 3) * 2;
                    int m  = wm * 64 + mi * 16 + (lane >> 2);
                    smemT[nn * 132 + m]           = acc[mi][ni][0];
                    smemT[(nn + 1) * 132 + m]     = acc[mi][ni][1];
                    smemT[nn * 132 + m + 8]       = acc[mi][ni][2];
                    smemT[(nn + 1) * 132 + m + 8] = acc[mi][ni][3];
                }
        }
        __syncthreads();

        int nloc = tid >> 3, grp = tid & 7;
        int n_g = n0 + c * 32 + nloc;
        float bz = __ldg(bias + n_g);
#pragma unroll
        for (int q = 0; q < 4; ++q) {
            int m = grp * 16 + q * 4;
            float4 v = *reinterpret_cast<const float4*>(&smemT[nloc * 132 + m]);
            v.x += bz; v.y += bz; v.z += bz; v.w += bz;
            int mg = m0 + m, wq = mg >> 6, bq = mg & 63;
            float* dst = reinterpret_cast<float*>(g_xp2) +
                         (((size_t)dir * WW + wq) * 1024 + n_g) * 64 + bq;
            *reinterpret_cast<float4*>(dst) = v;
        }
        __syncthreads();
    }
}

// ---------------------------------------------------------------------------
// Kernel 3: PERSISTENT bidirectional LSTM.
// Per-direction barrier counters (128 blocks each, 4 act-warp arrivals per
// block -> 512/step); arrivals per-warp right after own fence; next-step x
// gates prefetched before the spin (latency hidden under barrier wait).
// ---------------------------------------------------------------------------
__global__ void __launch_bounds__(256, 2)
lstm_persistent_kernel(const float* __restrict__ whhF,
                       const float* __restrict__ whhB,
                       float* __restrict__ out, int write_full)
{
    __shared__ ulonglong2 Wsh[64][32];   // 32 KB: [kq][r], r = gate*8 + jl
    __shared__ ulonglong2 Hsh[64][16];   // 16 KB: [kq][b]; overlaid by Psh

    float* Psh = reinterpret_cast<float*>(Hsh);  // [kc 4][r 32][b 16]

    int jt  = blockIdx.x;                // 0..31
    int bt  = blockIdx.y;                // 0..3
    int dir = blockIdx.z;
    int tid = threadIdx.x;
    const float* whh = dir ? whhB : whhF;

    for (int idx = tid; idx < 32 * 64; idx += 256) {
        int r = idx >> 6, kq = idx & 63;
        int grow = ((r >> 3) << 8) + (jt << 3) + (r & 7);
        *reinterpret_cast<float4*>(&Wsh[kq][r]) =
            *reinterpret_cast<const float4*>(whh + (size_t)grow * 256 + kq * 4);
    }

    int kc = tid >> 6;                   // 0..3
    int jl = (tid >> 3) & 7;             // 0..7
    int bg = tid & 7;                    // 0..7
    int b0 = bg << 1;

    int jl_a = tid >> 4;                 // 0..7
    int bl_a = tid & 15;                 // 0..15
    int bg_a = (bt << 4) + bl_a;
    int jg_a = (jt << 3) + jl_a;
    float c_reg = 0.f;

    const ulonglong2* hp = &Hsh[kc << 4][0];
    const ulonglong2* wp = &Wsh[kc << 4][0];

    // preload x gates for step 0
    float x_i = 0.f, x_f = 0.f, x_g = 0.f, x_o = 0.f;
    if (tid < 128) {
        int t0 = dir ? (WW - 1) : 0;
        const float* xb = &g_xp2[dir][t0][0][jg_a][bg_a];
        x_i = __ldg(xb);
        x_f = __ldg(xb + 1 * 256 * 64);
        x_g = __ldg(xb + 2 * 256 * 64);
        x_o = __ldg(xb + 3 * 256 * 64);
    }

    volatile unsigned* barp = &g_barD[dir];

    for (int step = 0; step < WW; ++step) {
        int t = dir ? (WW - 1 - step) : step;
        int phase_r = step & 1;

        // stage h_prev tile: coalesced K-major reads (L2-coherent path)
        if (step == 0) {
            for (int idx = tid; idx < 16 * 64; idx += 256) {
                int b = idx & 15, kq = idx >> 4;
                *reinterpret_cast<float4*>(&Hsh[kq][b]) = make_float4(0.f, 0.f, 0.f, 0.f);
            }
        } else {
            const float4* hsrc = reinterpret_cast<const float4*>(&g_h2[phase_r][dir][0][0][0]);
            for (int idx = tid; idx < 16 * 64; idx += 256) {
                int b = idx & 15, kq = idx >> 4;
                *reinterpret_cast<float4*>(&Hsh[kq][b]) =
                    __ldcg(hsrc + (size_t)kq * 64 + (bt << 4) + b);
            }
        }
        __syncthreads();

        unsigned long long a00 = 0ULL, a01 = 0ULL, a10 = 0ULL, a11 = 0ULL;
        unsigned long long a20 = 0ULL, a21 = 0ULL, a30 = 0ULL, a31 = 0ULL;
#pragma unroll
        for (int i = 0; i < 16; ++i) {
            ulonglong2 h0 = hp[(i << 4) + b0];
            ulonglong2 h1 = hp[(i << 4) + b0 + 1];
            ulonglong2 w0 = wp[(i << 5) + jl];
            ulonglong2 w1 = wp[(i << 5) + 8 + jl];
            ulonglong2 w2 = wp[(i << 5) + 16 + jl];
            ulonglong2 w3 = wp[(i << 5) + 24 + jl];
            fma2(a00, w0.x, h0.x); fma2(a00, w0.y, h0.y);
            fma2(a01, w0.x, h1.x); fma2(a01, w0.y, h1.y);
            fma2(a10, w1.x, h0.x); fma2(a10, w1.y, h0.y);
            fma2(a11, w1.x, h1.x); fma2(a11, w1.y, h1.y);
            fma2(a20, w2.x, h0.x); fma2(a20, w2.y, h0.y);
            fma2(a21, w2.x, h1.x); fma2(a21, w2.y, h1.y);
            fma2(a30, w3.x, h0.x); fma2(a30, w3.y, h0.y);
            fma2(a31, w3.x, h1.x); fma2(a31, w3.y, h1.y);
        }
        __syncthreads();   // Hsh reads done; safe to overlay with Psh

        {
            float2 u;
            int base = (kc << 9) + jl * 16;
            u = unpack2(a00); Psh[base + ( 0 << 4) + b0]     = u.x + u.y;
            u = unpack2(a01); Psh[base + ( 0 << 4) + b0 + 1] = u.x + u.y;
            u = unpack2(a10); Psh[base + ( 8 << 4) + b0]     = u.x + u.y;
            u = unpack2(a11); Psh[base + ( 8 << 4) + b0 + 1] = u.x + u.y;
            u = unpack2(a20); Psh[base + (16 << 4) + b0]     = u.x + u.y;
            u = unpack2(a21); Psh[base + (16 << 4) + b0 + 1] = u.x + u.y;
            u = unpack2(a30); Psh[base + (24 << 4) + b0]     = u.x + u.y;
            u = unpack2(a31); Psh[base + (24 << 4) + b0 + 1] = u.x + u.y;
        }
        __syncthreads();

        if (tid < 128) {
            int o = jl_a * 16 + bl_a;
            float gi = x_i, gf = x_f, gg = x_g, go = x_o;
#pragma unroll
            for (int k = 0; k < 4; ++k) {
                int base = (k << 9) + o;
                gi += Psh[base];
                gf += Psh[base + (8 << 4)];
                gg += Psh[base + (16 << 4)];
                go += Psh[base + (24 << 4)];
            }
            float ig = 1.f / (1.f + expf(-gi));
            float fg = 1.f / (1.f + expf(-gf));
            float tg = tanhf(gg);
            float og = 1.f / (1.f + expf(-go));
            c_reg = fg * c_reg + ig * tg;
            float h = og * tanhf(c_reg);

            g_h2[phase_r ^ 1][dir][jg_a >> 2][bg_a][jg_a & 3] = h;
            size_t bw = (size_t)bg_a * WW + t;
            out[bw * 512 + (dir << 8) + jg_a] = h;
            if (write_full)
                out[OUT_RNN1_SZ + (size_t)dir * OUT_H_SZ + bw * HH + jg_a] = h;

            // per-warp release + arrival (4 act warps per block)
            __threadfence();
            if ((tid & 31) == 0) atomicAdd((unsigned*)barp, 1u);

            // prefetch next step's x gates (flies during the spin)
            if (step + 1 < WW) {
                int tn = dir ? (WW - 2 - step) : (step + 1);
                const float* xb = &g_xp2[dir][tn][0][jg_a][bg_a];
                x_i = __ldg(xb);
                x_f = __ldg(xb + 1 * 256 * 64);
                x_g = __ldg(xb + 2 * 256 * 64);
                x_o = __ldg(xb + 3 * 256 * 64);
            }
        }

        if (step < WW - 1) {
            if (tid == 0) {
                unsigned target = (unsigned)(step + 1) * 512u;
                while (*barp < target) { }
            }
            __syncthreads();
        }
    }
}

// ---------------------------------------------------------------------------
extern "C" void kernel_launch(void* const* d_in, const int* in_sizes, int n_in,
                              void* d_out, int out_size)
{
    const int*   words      = (const int*)  d_in[0];
    const float* features   = (const float*)d_in[1];
    const int*   lip        = (const int*)  d_in[2];
    const int*   postags    = (const int*)  d_in[3];
    // d_in[4] = chars (unused), d_in[5] = masks (unused)
    const float* word_table = (const float*)d_in[6];
    const float* pos_table  = (const float*)d_in[7];
    const float* w_ih_f     = (const float*)d_in[8];
    const float* w_hh_f     = (const float*)d_in[9];
    const float* b_f        = (const float*)d_in[10];
    const float* w_ih_b     = (const float*)d_in[11];
    const float* w_hh_b     = (const float*)d_in[12];
    const float* b_b        = (const float*)d_in[13];
    float* out = (float*)d_out;

    int write_full = ((size_t)out_size >= OUT_TOTAL) ? 1 : 0;

    cudaFuncSetAttribute((const void*)tc_gemm_kernel,
                         cudaFuncAttributeMaxDynamicSharedMemorySize, SMEM_GEMM);

    // Phase 1: embeddings (bf16 hi/lo split) + weight split + barrier reset
    embed_kernel<<<ROWS, 128>>>(words, features, lip, postags, word_table, pos_table);
    prep_w_kernel<<<dim3(NG, 2), 128>>>(w_ih_f, w_ih_b);

    // Phase 2: input projections on tensor cores (mma.sync bf16 split)
    tc_gemm_kernel<<<dim3(8, 127, 2), 256, SMEM_GEMM>>>(b_f, b_b);

    // Phase 3: persistent recurrence, single launch
    lstm_persistent_kernel<<<dim3(32, 4, 2), 256>>>(w_hh_f, w_hh_b, out, write_full);
}